// round 1
// baseline (speedup 1.0000x reference)
#include <cuda_runtime.h>

#define WIN   400
#define HOP   100
#define PAD   300          // WIN - HOP
#define T_IN  480000
#define BATCH 32
#define C_OUT 514          // 2*(512/2+1)
#define F_OUT 4803         // floor((480600-400)/100)+1

#define TILE_C 32
#define TILE_F 64
#define THREADS 128
#define SX_LEN ((TILE_F - 1) * HOP + WIN)   // 6700 floats
#define SW_PITCH (TILE_C + 1)               // 33, pad to kill bank conflicts
#define SMEM_BYTES ((SX_LEN + WIN * SW_PITCH) * sizeof(float))  // 79600 B

__global__ __launch_bounds__(THREADS, 2)
void conv_stft_kernel(const float* __restrict__ x,
                      const float* __restrict__ w,
                      float* __restrict__ out)
{
    extern __shared__ float smem[];
    float* sx = smem;                 // [SX_LEN]
    float* sw = smem + SX_LEN;        // [WIN][SW_PITCH] transposed weights

    const int b   = blockIdx.z;
    const int c0  = blockIdx.y * TILE_C;
    const int f0  = blockIdx.x * TILE_F;
    const int tid = threadIdx.x;

    // ---- load input segment (with zero padding at sequence edges) ----
    const long long x_start = (long long)f0 * HOP - PAD;
    const float* xb = x + (size_t)b * T_IN;
    #pragma unroll 4
    for (int i = tid; i < SX_LEN; i += THREADS) {
        long long gi = x_start + i;
        sx[i] = (gi >= 0 && gi < T_IN) ? xb[gi] : 0.0f;
    }

    // ---- load weight tile, transposed: sw[k*33 + c] = w[(c0+c)*WIN + k] ----
    // global reads coalesced along k; smem writes stride 33 -> conflict-free
    #pragma unroll 4
    for (int i = tid; i < TILE_C * WIN; i += THREADS) {
        int c = i / WIN;
        int k = i - c * WIN;
        int gc = c0 + c;
        sw[k * SW_PITCH + c] = (gc < C_OUT) ? w[(size_t)gc * WIN + k] : 0.0f;
    }
    __syncthreads();

    // ---- 4x4 register tile per thread ----
    const int tx = tid & 7;          // channel group 0..7  -> channels cb..cb+3
    const int ty = tid >> 3;         // frame   group 0..15 -> frames  fb..fb+3
    const int cb = tx * 4;
    const int fb = ty * 4;

    float acc[4][4];
    #pragma unroll
    for (int i = 0; i < 4; i++)
        #pragma unroll
        for (int j = 0; j < 4; j++)
            acc[i][j] = 0.0f;

    const int xoff0 = (fb + 0) * HOP;
    const int xoff1 = (fb + 1) * HOP;
    const int xoff2 = (fb + 2) * HOP;
    const int xoff3 = (fb + 3) * HOP;

    #pragma unroll 4
    for (int k = 0; k < WIN; k++) {
        const float* swk = sw + k * SW_PITCH + cb;
        float w0 = swk[0];
        float w1 = swk[1];
        float w2 = swk[2];
        float w3 = swk[3];

        float x0 = sx[xoff0 + k];
        float x1 = sx[xoff1 + k];
        float x2 = sx[xoff2 + k];
        float x3 = sx[xoff3 + k];

        acc[0][0] = fmaf(w0, x0, acc[0][0]);
        acc[0][1] = fmaf(w0, x1, acc[0][1]);
        acc[0][2] = fmaf(w0, x2, acc[0][2]);
        acc[0][3] = fmaf(w0, x3, acc[0][3]);
        acc[1][0] = fmaf(w1, x0, acc[1][0]);
        acc[1][1] = fmaf(w1, x1, acc[1][1]);
        acc[1][2] = fmaf(w1, x2, acc[1][2]);
        acc[1][3] = fmaf(w1, x3, acc[1][3]);
        acc[2][0] = fmaf(w2, x0, acc[2][0]);
        acc[2][1] = fmaf(w2, x1, acc[2][1]);
        acc[2][2] = fmaf(w2, x2, acc[2][2]);
        acc[2][3] = fmaf(w2, x3, acc[2][3]);
        acc[3][0] = fmaf(w3, x0, acc[3][0]);
        acc[3][1] = fmaf(w3, x1, acc[3][1]);
        acc[3][2] = fmaf(w3, x2, acc[3][2]);
        acc[3][3] = fmaf(w3, x3, acc[3][3]);
    }

    // ---- store (guard ragged edges: C=514 -> last c-tile has 2; F=4803 -> last f-tile has 3) ----
    #pragma unroll
    for (int i = 0; i < 4; i++) {
        int c = c0 + cb + i;
        if (c >= C_OUT) continue;
        size_t base = ((size_t)b * C_OUT + c) * F_OUT;
        #pragma unroll
        for (int j = 0; j < 4; j++) {
            int f = f0 + fb + j;
            if (f < F_OUT) out[base + f] = acc[i][j];
        }
    }
}

extern "C" void kernel_launch(void* const* d_in, const int* in_sizes, int n_in,
                              void* d_out, int out_size)
{
    const float* x = (const float*)d_in[0];   // [32, 480000]
    const float* w = (const float*)d_in[1];   // [514, 1, 400]
    float* out = (float*)d_out;               // [32, 514, 4803]

    cudaFuncSetAttribute(conv_stft_kernel,
                         cudaFuncAttributeMaxDynamicSharedMemorySize,
                         (int)SMEM_BYTES);

    dim3 grid((F_OUT + TILE_F - 1) / TILE_F,   // 76
              (C_OUT + TILE_C - 1) / TILE_C,   // 17
              BATCH);                          // 32
    conv_stft_kernel<<<grid, THREADS, SMEM_BYTES>>>(x, w, out);
}

// round 3
// speedup vs baseline: 3.1142x; 3.1142x over previous
#include <cuda_runtime.h>
#include <cuda_bf16.h>
#include <cstdint>

// ---------------- problem constants ----------------
#define WIN     400
#define HOP     100
#define PADL    300
#define T_IN    480000
#define BATCH   32
#define C_OUT   514
#define F_OUT   4803

#define KPAD    448               // 7 chunks of 64; zeros beyond 400
#define MPAD    640               // 5 * 128 channel rows
#define XPAD    486784            // padded signal: 300 zeros + 480000 + zeros (covers all tiles)

#define TILE_M  128
#define TILE_N  64
#define NT_C    5
#define NT_F    76                // ceil(4803/64)
#define THREADS 256

// ---------------- device scratch ----------------
__device__ __nv_bfloat16 g_wh[MPAD * KPAD];
__device__ __nv_bfloat16 g_wl[MPAD * KPAD];
__device__ __nv_bfloat16 g_xh[BATCH * (size_t)XPAD];
__device__ __nv_bfloat16 g_xl[BATCH * (size_t)XPAD];

// ---------------- smem layout (bytes) ----------------
// input segment: (TILE_N-1)*100 + 448 = 6748 -> 6752 elems
#define SX_ELEMS   6752
#define SX_BYTES   (SX_ELEMS * 2)      // 13504
#define PITCH_B    144                 // 72 bf16: conflict-free ldmatrix, 16B-aligned
#define OFF_SXH    0
#define OFF_SXL    13504
#define OFF_AH     27008               // 128 rows * 144B = 18432
#define OFF_AL     45440
#define OFF_BH     63872               // 64 rows * 144B = 9216
#define OFF_BL     73088
#define SMEM_TOTAL 82304

// ---------------- helpers ----------------
__device__ __forceinline__ uint32_t smem_u32(const void* p) {
    uint32_t a;
    asm("{ .reg .u64 t; cvta.to.shared.u64 t, %1; cvt.u32.u64 %0, t; }" : "=r"(a) : "l"(p));
    return a;
}

__device__ __forceinline__ void ldsm_x4(uint32_t& r0, uint32_t& r1, uint32_t& r2, uint32_t& r3,
                                        uint32_t addr) {
    asm volatile("ldmatrix.sync.aligned.m8n8.x4.shared.b16 {%0,%1,%2,%3}, [%4];"
                 : "=r"(r0), "=r"(r1), "=r"(r2), "=r"(r3) : "r"(addr));
}
__device__ __forceinline__ void ldsm_x2(uint32_t& r0, uint32_t& r1, uint32_t addr) {
    asm volatile("ldmatrix.sync.aligned.m8n8.x2.shared.b16 {%0,%1}, [%2];"
                 : "=r"(r0), "=r"(r1) : "r"(addr));
}
__device__ __forceinline__ void mma16816(float* d, const uint32_t* a, const uint32_t* b) {
    asm volatile(
        "mma.sync.aligned.m16n8k16.row.col.f32.bf16.bf16.f32 "
        "{%0,%1,%2,%3}, {%4,%5,%6,%7}, {%8,%9}, {%0,%1,%2,%3};"
        : "+f"(d[0]), "+f"(d[1]), "+f"(d[2]), "+f"(d[3])
        : "r"(a[0]), "r"(a[1]), "r"(a[2]), "r"(a[3]), "r"(b[0]), "r"(b[1]));
}

// ---------------- prep kernels: fp32 -> (bf16 hi, bf16 lo) ----------------
__global__ void prep_w_kernel(const float* __restrict__ w) {
    int idx = blockIdx.x * blockDim.x + threadIdx.x;
    if (idx >= MPAD * KPAD) return;
    int c = idx / KPAD;
    int k = idx - c * KPAD;
    float v = (c < C_OUT && k < WIN) ? w[c * WIN + k] : 0.0f;
    __nv_bfloat16 h = __float2bfloat16(v);
    g_wh[idx] = h;
    g_wl[idx] = __float2bfloat16(v - __bfloat162float(h));
}

__global__ void prep_x_kernel(const float* __restrict__ x) {
    size_t idx = (size_t)blockIdx.x * blockDim.x + threadIdx.x;
    if (idx >= (size_t)BATCH * XPAD) return;
    int b = (int)(idx / XPAD);
    int i = (int)(idx - (size_t)b * XPAD);
    int src = i - PADL;
    float v = (src >= 0 && src < T_IN) ? x[(size_t)b * T_IN + src] : 0.0f;
    __nv_bfloat16 h = __float2bfloat16(v);
    g_xh[idx] = h;
    g_xl[idx] = __float2bfloat16(v - __bfloat162float(h));
}

// ---------------- main HMMA GEMM kernel ----------------
__global__ __launch_bounds__(THREADS, 2)
void conv_stft_hmma_kernel(float* __restrict__ out)
{
    extern __shared__ char smem[];
    const uint32_t sbase = smem_u32(smem);
    const int tid  = threadIdx.x;
    const int wid  = tid >> 5;
    const int lane = tid & 31;

    const int c0 = blockIdx.x * TILE_M;
    const int f0 = blockIdx.y * TILE_N;
    const int b  = blockIdx.z;

    // ---- load overlapping input segment (both splits) ----
    {
        const int gbase = f0 * HOP;      // multiple of 8 (64*100)
        const uint4* gxh = reinterpret_cast<const uint4*>(g_xh + (size_t)b * XPAD + gbase);
        const uint4* gxl = reinterpret_cast<const uint4*>(g_xl + (size_t)b * XPAD + gbase);
        uint4* sxh = reinterpret_cast<uint4*>(smem + OFF_SXH);
        uint4* sxl = reinterpret_cast<uint4*>(smem + OFF_SXL);
        #pragma unroll 2
        for (int i = tid; i < SX_ELEMS / 8; i += THREADS) {   // 844 vectors
            sxh[i] = gxh[i];
            sxl[i] = gxl[i];
        }
    }

    // warp tile: 4 (M) x 2 (N) warps, each 32x32
    const int m0 = (wid >> 1) * 32;
    const int n0 = (wid & 1) * 32;

    float acc[2][4][4];
    #pragma unroll
    for (int i = 0; i < 2; i++)
        #pragma unroll
        for (int j = 0; j < 4; j++)
            #pragma unroll
            for (int q = 0; q < 4; q++) acc[i][j][q] = 0.0f;

    // per-lane ldmatrix base addresses
    const uint32_t a_row = m0 + (lane & 15);
    const uint32_t a_colh = (lane >> 4) * 16;
    const uint32_t ah_base = sbase + OFF_AH + a_row * PITCH_B + a_colh;
    const uint32_t al_base = sbase + OFF_AL + a_row * PITCH_B + a_colh;
    const uint32_t b_row = n0 + (lane & 7);
    const uint32_t b_colh = ((lane >> 3) & 1) * 16;
    const uint32_t bh_base = sbase + OFF_BH + b_row * PITCH_B + b_colh;
    const uint32_t bl_base = sbase + OFF_BL + b_row * PITCH_B + b_colh;

    for (int kc = 0; kc < 7; kc++) {
        __syncthreads();   // sx ready (kc=0) / previous chunk compute done (kc>0)

        // ---- stage A chunk: 128 rows x 64 bf16, both splits ----
        {
            const uint4* gwh = reinterpret_cast<const uint4*>(g_wh);
            const uint4* gwl = reinterpret_cast<const uint4*>(g_wl);
            #pragma unroll
            for (int i = tid; i < TILE_M * 8; i += THREADS) {   // 1024 uint4
                int r = i >> 3, u = i & 7;
                int gv = ((c0 + r) * KPAD + kc * 64) / 8 + u;
                char* dst = smem + OFF_AH + r * PITCH_B + u * 16;
                *reinterpret_cast<uint4*>(dst) = gwh[gv];
                *reinterpret_cast<uint4*>(dst + (OFF_AL - OFF_AH)) = gwl[gv];
            }
        }
        // ---- stage B chunk from sx (im2col, smem->smem): 64 frames x 64 bf16 ----
        {
            #pragma unroll
            for (int i = tid; i < TILE_N * 16; i += THREADS) {  // 1024 uint2
                int f = i >> 4, u = i & 15;
                int soff = (f * HOP + kc * 64 + u * 4) * 2;     // bytes, 8B-aligned
                uint2 vh = *reinterpret_cast<const uint2*>(smem + OFF_SXH + soff);
                uint2 vl = *reinterpret_cast<const uint2*>(smem + OFF_SXL + soff);
                char* dst = smem + OFF_BH + f * PITCH_B + u * 8;
                *reinterpret_cast<uint2*>(dst) = vh;
                *reinterpret_cast<uint2*>(dst + (OFF_BL - OFF_BH)) = vl;
            }
        }
        __syncthreads();

        // ---- compute: 4 k-steps of 16 ----
        #pragma unroll
        for (int ks = 0; ks < 4; ks++) {
            uint32_t ah[2][4], al[2][4], bh[4][2], bl[4][2];
            #pragma unroll
            for (int mi = 0; mi < 2; mi++) {
                ldsm_x4(ah[mi][0], ah[mi][1], ah[mi][2], ah[mi][3],
                        ah_base + mi * 16 * PITCH_B + ks * 32);
                ldsm_x4(al[mi][0], al[mi][1], al[mi][2], al[mi][3],
                        al_base + mi * 16 * PITCH_B + ks * 32);
            }
            #pragma unroll
            for (int ni = 0; ni < 4; ni++) {
                ldsm_x2(bh[ni][0], bh[ni][1], bh_base + ni * 8 * PITCH_B + ks * 32);
                ldsm_x2(bl[ni][0], bl[ni][1], bl_base + ni * 8 * PITCH_B + ks * 32);
            }
            #pragma unroll
            for (int mi = 0; mi < 2; mi++)
                #pragma unroll
                for (int ni = 0; ni < 4; ni++) {
                    mma16816(acc[mi][ni], ah[mi], bh[ni]);   // h*h
                    mma16816(acc[mi][ni], ah[mi], bl[ni]);   // h*l
                    mma16816(acc[mi][ni], al[mi], bh[ni]);   // l*h
                }
        }
    }

    // ---- store: D rows = channels, cols = frames ----
    const int g = lane >> 2;
    const int t = lane & 3;
    #pragma unroll
    for (int mi = 0; mi < 2; mi++) {
        #pragma unroll
        for (int ni = 0; ni < 4; ni++) {
            int f = f0 + n0 + ni * 8 + t * 2;
            #pragma unroll
            for (int half = 0; half < 2; half++) {
                int c = c0 + m0 + mi * 16 + g + half * 8;
                if (c < C_OUT && f < F_OUT) {
                    size_t base = ((size_t)b * C_OUT + c) * F_OUT + f;
                    out[base] = acc[mi][ni][half * 2];
                    if (f + 1 < F_OUT) out[base + 1] = acc[mi][ni][half * 2 + 1];
                }
            }
        }
    }
}

// ---------------- launcher ----------------
extern "C" void kernel_launch(void* const* d_in, const int* in_sizes, int n_in,
                              void* d_out, int out_size)
{
    const float* x = (const float*)d_in[0];   // [32, 480000]
    const float* w = (const float*)d_in[1];   // [514, 1, 400]
    float* out = (float*)d_out;               // [32, 514, 4803]

    prep_w_kernel<<<(MPAD * KPAD + 255) / 256, 256>>>(w);
    prep_x_kernel<<<(int)(((size_t)BATCH * XPAD + 255) / 256), 256>>>(x);

    cudaFuncSetAttribute(conv_stft_hmma_kernel,
                         cudaFuncAttributeMaxDynamicSharedMemorySize, SMEM_TOTAL);

    dim3 grid(NT_C, NT_F, BATCH);   // 5 x 76 x 32
    conv_stft_hmma_kernel<<<grid, THREADS, SMEM_TOTAL>>>(out);
}

// round 4
// speedup vs baseline: 3.4714x; 1.1147x over previous
#include <cuda_runtime.h>
#include <cuda_bf16.h>
#include <cstdint>

// ---------------- problem constants ----------------
#define WIN     400
#define HOP     100
#define PADL    300
#define T_IN    480000
#define BATCH   32
#define C_OUT   514
#define F_OUT   4803

#define KPAD    448               // 7 chunks of 64; zeros beyond 400
#define MPAD    640               // 5 * 128 channel rows
#define XPAD    486784            // 300 zeros + signal + tail zeros (covers all tiles)

#define TILE_M  128
#define TILE_N  128
#define NT_C    5
#define NT_F    38                // ceil(4803/128)
#define THREADS 512

// ---------------- device scratch ----------------
__device__ __nv_bfloat16 g_wh[MPAD * KPAD];
__device__ __nv_bfloat16 g_wl[MPAD * KPAD];
__device__ __nv_bfloat16 g_xh[BATCH * (size_t)XPAD];
__device__ __nv_bfloat16 g_xl[BATCH * (size_t)XPAD];

// ---------------- smem layout ----------------
// pitch per row of 64 bf16: 128B data + 16B pad (ldmatrix conflict-free)
#define PITCH_B     144
#define SPLIT_BYTES (128 * PITCH_B)            // 18432 (one split, one stage)
#define STAGE_BYTES (2 * SPLIT_BYTES)          // h + l
#define OFF_A(s)    ((s) * STAGE_BYTES)        // A: stages 0,1
#define OFF_B(s)    (73728 + (s) * STAGE_BYTES)
#define SMEM_TOTAL  147456
#define EPI_PITCH   129                        // floats

// ---------------- helpers ----------------
__device__ __forceinline__ uint32_t smem_u32(const void* p) {
    uint32_t a;
    asm("{ .reg .u64 t; cvta.to.shared.u64 t, %1; cvt.u32.u64 %0, t; }" : "=r"(a) : "l"(p));
    return a;
}
__device__ __forceinline__ void cp16(uint32_t dst, const void* src) {
    asm volatile("cp.async.cg.shared.global [%0], [%1], 16;" :: "r"(dst), "l"(src));
}
__device__ __forceinline__ void cp8(uint32_t dst, const void* src) {
    asm volatile("cp.async.ca.shared.global [%0], [%1], 8;" :: "r"(dst), "l"(src));
}
__device__ __forceinline__ void cp_commit() {
    asm volatile("cp.async.commit_group;" ::: "memory");
}
template <int N>
__device__ __forceinline__ void cp_wait() {
    asm volatile("cp.async.wait_group %0;" :: "n"(N) : "memory");
}
__device__ __forceinline__ void ldsm_x4(uint32_t& r0, uint32_t& r1, uint32_t& r2, uint32_t& r3,
                                        uint32_t addr) {
    asm volatile("ldmatrix.sync.aligned.m8n8.x4.shared.b16 {%0,%1,%2,%3}, [%4];"
                 : "=r"(r0), "=r"(r1), "=r"(r2), "=r"(r3) : "r"(addr));
}
__device__ __forceinline__ void mma16816(float* d, const uint32_t* a, const uint32_t* b) {
    asm volatile(
        "mma.sync.aligned.m16n8k16.row.col.f32.bf16.bf16.f32 "
        "{%0,%1,%2,%3}, {%4,%5,%6,%7}, {%8,%9}, {%0,%1,%2,%3};"
        : "+f"(d[0]), "+f"(d[1]), "+f"(d[2]), "+f"(d[3])
        : "r"(a[0]), "r"(a[1]), "r"(a[2]), "r"(a[3]), "r"(b[0]), "r"(b[1]));
}

// ---------------- prep kernels: fp32 -> (bf16 hi, bf16 lo) ----------------
__global__ void prep_w_kernel(const float* __restrict__ w) {
    int idx = blockIdx.x * blockDim.x + threadIdx.x;
    if (idx >= MPAD * KPAD) return;
    int c = idx / KPAD;
    int k = idx - c * KPAD;
    float v = (c < C_OUT && k < WIN) ? w[c * WIN + k] : 0.0f;
    __nv_bfloat16 h = __float2bfloat16(v);
    g_wh[idx] = h;
    g_wl[idx] = __float2bfloat16(v - __bfloat162float(h));
}

__global__ void prep_x_kernel(const float* __restrict__ x) {
    size_t idx = (size_t)blockIdx.x * blockDim.x + threadIdx.x;
    if (idx >= (size_t)BATCH * XPAD) return;
    int b = (int)(idx / XPAD);
    int i = (int)(idx - (size_t)b * XPAD);
    int src = i - PADL;
    float v = (src >= 0 && src < T_IN) ? x[(size_t)b * T_IN + src] : 0.0f;
    __nv_bfloat16 h = __float2bfloat16(v);
    g_xh[idx] = h;
    g_xl[idx] = __float2bfloat16(v - __bfloat162float(h));
}

// ---------------- main pipelined HMMA GEMM kernel ----------------
__global__ __launch_bounds__(THREADS, 1)
void conv_stft_hmma_kernel(float* __restrict__ out)
{
    extern __shared__ char smem[];
    const uint32_t sbase = smem_u32(smem);
    const int tid  = threadIdx.x;
    const int wid  = tid >> 5;
    const int lane = tid & 31;

    const int c0 = blockIdx.x * TILE_M;
    const int f0 = blockIdx.y * TILE_N;
    const int b  = blockIdx.z;

    const char* wh_base = reinterpret_cast<const char*>(g_wh) + (size_t)c0 * KPAD * 2;
    const char* wl_base = reinterpret_cast<const char*>(g_wl) + (size_t)c0 * KPAD * 2;
    const char* xh_base = reinterpret_cast<const char*>(g_xh + (size_t)b * XPAD + f0 * HOP);
    const char* xl_base = reinterpret_cast<const char*>(g_xl + (size_t)b * XPAD + f0 * HOP);

    // ---- stage one K-chunk (64 wide) into double-buffer stage s ----
    auto stage = [&](int kc, int s) {
        // A: 128 rows x 64 bf16, both splits; 16B cp.async, 2048 ops
        #pragma unroll
        for (int i = tid; i < 2 * TILE_M * 8; i += THREADS) {
            int split = i >> 10;
            int j = i & 1023;
            int r = j >> 3, u = j & 7;
            const char* src = (split ? wl_base : wh_base) + r * (KPAD * 2) + kc * 128 + u * 16;
            cp16(sbase + OFF_A(s) + split * SPLIT_BYTES + r * PITCH_B + u * 16, src);
        }
        // B: 128 frame-rows x 64 bf16, both splits; 8B cp.async (row base only 8B-aligned)
        #pragma unroll
        for (int i = tid; i < 2 * TILE_N * 16; i += THREADS) {
            int split = i >> 11;
            int j = i & 2047;
            int f = j >> 4, u = j & 15;
            const char* src = (split ? xl_base : xh_base) + f * (HOP * 2) + kc * 128 + u * 8;
            cp8(sbase + OFF_B(s) + split * SPLIT_BYTES + f * PITCH_B + u * 8, src);
        }
        cp_commit();
    };

    // warp tile: 4 (M) x 4 (N) warps, each 32x32
    const int m0 = (wid >> 2) * 32;
    const int n0 = (wid & 3) * 32;

    float acc[2][4][4];
    #pragma unroll
    for (int i = 0; i < 2; i++)
        #pragma unroll
        for (int j = 0; j < 4; j++)
            #pragma unroll
            for (int q = 0; q < 4; q++) acc[i][j][q] = 0.0f;

    // per-lane ldmatrix offsets (within a split region)
    const uint32_t a_off = (m0 + (lane & 15)) * PITCH_B + (lane >> 4) * 16;
    const uint32_t b_off = (n0 + ((lane >> 4) << 3) + (lane & 7)) * PITCH_B + ((lane >> 3) & 1) * 16;

    stage(0, 0);

    for (int kc = 0; kc < 7; kc++) {
        const int s = kc & 1;
        if (kc < 6) stage(kc + 1, s ^ 1);
        if (kc < 6) cp_wait<1>(); else cp_wait<0>();
        __syncthreads();

        const uint32_t ah_base = sbase + OFF_A(s) + a_off;
        const uint32_t al_base = ah_base + SPLIT_BYTES;
        const uint32_t bh_base = sbase + OFF_B(s) + b_off;
        const uint32_t bl_base = bh_base + SPLIT_BYTES;

        #pragma unroll
        for (int ks = 0; ks < 4; ks++) {
            uint32_t ah[2][4], al[2][4], bh[2][4], bl[2][4];
            #pragma unroll
            for (int mi = 0; mi < 2; mi++) {
                ldsm_x4(ah[mi][0], ah[mi][1], ah[mi][2], ah[mi][3],
                        ah_base + mi * 16 * PITCH_B + ks * 32);
                ldsm_x4(al[mi][0], al[mi][1], al[mi][2], al[mi][3],
                        al_base + mi * 16 * PITCH_B + ks * 32);
            }
            #pragma unroll
            for (int np = 0; np < 2; np++) {     // each x4 covers 2 n8-tiles
                ldsm_x4(bh[np][0], bh[np][1], bh[np][2], bh[np][3],
                        bh_base + np * 16 * PITCH_B + ks * 32);
                ldsm_x4(bl[np][0], bl[np][1], bl[np][2], bl[np][3],
                        bl_base + np * 16 * PITCH_B + ks * 32);
            }
            #pragma unroll
            for (int mi = 0; mi < 2; mi++)
                #pragma unroll
                for (int ni = 0; ni < 4; ni++) {
                    const uint32_t* bhf = &bh[ni >> 1][(ni & 1) * 2];
                    const uint32_t* blf = &bl[ni >> 1][(ni & 1) * 2];
                    mma16816(acc[mi][ni], ah[mi], bhf);   // h*h
                    mma16816(acc[mi][ni], ah[mi], blf);   // h*l
                    mma16816(acc[mi][ni], al[mi], bhf);   // l*h
                }
        }
        if (kc < 6) __syncthreads();   // protect buffer s before it is re-staged
    }

    // ---- epilogue: registers -> smem (transpose) -> coalesced global stores ----
    __syncthreads();
    float* epi = reinterpret_cast<float*>(smem);
    const int g = lane >> 2;
    const int t = lane & 3;
    #pragma unroll
    for (int mi = 0; mi < 2; mi++)
        #pragma unroll
        for (int ni = 0; ni < 4; ni++) {
            int col = n0 + ni * 8 + t * 2;
            #pragma unroll
            for (int half = 0; half < 2; half++) {
                int row = m0 + mi * 16 + half * 8 + g;
                epi[row * EPI_PITCH + col]     = acc[mi][ni][half * 2];
                epi[row * EPI_PITCH + col + 1] = acc[mi][ni][half * 2 + 1];
            }
        }
    __syncthreads();

    #pragma unroll 4
    for (int idx = tid; idx < TILE_M * TILE_N; idx += THREADS) {
        int row = idx >> 7;
        int col = idx & 127;
        int c = c0 + row;
        int f = f0 + col;
        if (c < C_OUT && f < F_OUT)
            out[((size_t)b * C_OUT + c) * F_OUT + f] = epi[row * EPI_PITCH + col];
    }
}

// ---------------- launcher ----------------
extern "C" void kernel_launch(void* const* d_in, const int* in_sizes, int n_in,
                              void* d_out, int out_size)
{
    const float* x = (const float*)d_in[0];   // [32, 480000]
    const float* w = (const float*)d_in[1];   // [514, 1, 400]
    float* out = (float*)d_out;               // [32, 514, 4803]

    prep_w_kernel<<<(MPAD * KPAD + 255) / 256, 256>>>(w);
    prep_x_kernel<<<(int)(((size_t)BATCH * XPAD + 255) / 256), 256>>>(x);

    cudaFuncSetAttribute(conv_stft_hmma_kernel,
                         cudaFuncAttributeMaxDynamicSharedMemorySize, SMEM_TOTAL);

    dim3 grid(NT_C, NT_F, BATCH);   // 5 x 38 x 32 = 6080 CTAs, 41 waves
    conv_stft_hmma_kernel<<<grid, THREADS, SMEM_TOTAL>>>(out);
}